// round 16
// baseline (speedup 1.0000x reference)
#include <cuda_runtime.h>
#include <cuda_fp16.h>
#include <cstdint>

#define D_IN  128
#define D_HID 512
#define D_OUT 256
#define NMAX  100000
#define EMAX  1600000
#define MPAD  100096   // ceil(100000/128)*128

// ---------------- scratch (device globals; zero-initialized at load) --------
// Invariants across graph replays: g_deg==0, g_sum/g_sq==0 on entry.
__device__ int      g_deg[NMAX + 1];
__device__ int      g_off[NMAX + 1];
__device__ int      g_rank[EMAX];
__device__ int      g_bsum[128];
__device__ uint2    g_edge[EMAX];                          // (src, w-bits)
__device__ uint32_t g_xh [(size_t)NMAX * (D_IN / 2)];      // x fp16 [n][k/2]
__device__ uint32_t g_hin[(size_t)MPAD * (D_IN / 2)];      // half2 [m][k/2]
__device__ uint32_t g_h1h[(size_t)MPAD * (D_HID / 2)];     // h1 fp16 pre-BN
__device__ uint32_t g_w1t[(size_t)D_HID * (D_IN / 2)];     // w1^T fp16 [n][k/2]
__device__ uint32_t g_w2t[(size_t)D_OUT * (D_HID / 2)];    // w2^T fp16 [n][k/2]
__device__ float    g_sum[D_HID], g_sq[D_HID];
__device__ __half   g_sch[D_HID], g_shh[D_HID];            // BN scale/shift fp16

__device__ __forceinline__ uint32_t pack_h2(float a, float b) {
    __half2 h = __floats2half2_rn(a, b);
    return *reinterpret_cast<uint32_t*>(&h);
}
__device__ __forceinline__ uint32_t smem_u32(const void* p) {
    uint32_t a;
    asm("{ .reg .u64 t; cvta.to.shared.u64 t, %1; cvt.u32.u64 %0, t; }"
        : "=r"(a) : "l"(p));
    return a;
}
#define CP16(dst, src) \
    asm volatile("cp.async.cg.shared.global [%0], [%1], 16;" :: "r"(dst), "l"(src))
#define CP_COMMIT() asm volatile("cp.async.commit_group;" ::: "memory")
#define CP_WAIT0()  asm volatile("cp.async.wait_group 0;" ::: "memory")
#define CP_WAIT1()  asm volatile("cp.async.wait_group 1;" ::: "memory")

__device__ __forceinline__ void ldsm4(uint32_t& r0, uint32_t& r1,
                                      uint32_t& r2, uint32_t& r3, uint32_t a) {
    asm volatile("ldmatrix.sync.aligned.m8n8.x4.shared.b16 {%0,%1,%2,%3}, [%4];"
                 : "=r"(r0), "=r"(r1), "=r"(r2), "=r"(r3) : "r"(a));
}
__device__ __forceinline__ void mma_f16(float d[4], const uint32_t a[4],
                                        const uint32_t b[2]) {
    asm volatile(
        "mma.sync.aligned.m16n8k16.row.col.f32.f16.f16.f32 "
        "{%0,%1,%2,%3},{%4,%5,%6,%7},{%8,%9},{%0,%1,%2,%3};\n"
        : "+f"(d[0]), "+f"(d[1]), "+f"(d[2]), "+f"(d[3])
        : "r"(a[0]), "r"(a[1]), "r"(a[2]), "r"(a[3]),
          "r"(b[0]), "r"(b[1]));
}

// ------- merged prep: x->fp16 + w1^T + w2^T + degree histogram + ranks -------
__global__ void prep_kernel(const float* __restrict__ x,
                            const float* __restrict__ w1,
                            const float* __restrict__ w2,
                            const int* __restrict__ edst,
                            int nx, int E) {
    int i = blockIdx.x * 256 + threadIdx.x;
    if (i < nx) {
        float2 v = ((const float2*)x)[i];
        g_xh[i] = pack_h2(v.x, v.y);
    }
    if (i < D_HID * (D_IN / 2)) {
        int n = i / (D_IN / 2), kc = i % (D_IN / 2);
        g_w1t[i] = pack_h2(w1[(size_t)(2 * kc) * D_HID + n],
                           w1[(size_t)(2 * kc + 1) * D_HID + n]);
    }
    if (i < D_OUT * (D_HID / 2)) {
        int n = i / (D_HID / 2), kc = i % (D_HID / 2);
        g_w2t[i] = pack_h2(w2[(size_t)(2 * kc) * D_OUT + n],
                           w2[(size_t)(2 * kc + 1) * D_OUT + n]);
    }
    int i4 = i * 4;
    if (i4 + 4 <= E) {
        int4 d = *(const int4*)(edst + i4);
        int4 r;
        r.x = atomicAdd(&g_deg[d.x], 1);
        r.y = atomicAdd(&g_deg[d.y], 1);
        r.z = atomicAdd(&g_deg[d.z], 1);
        r.w = atomicAdd(&g_deg[d.w], 1);
        *(int4*)(g_rank + i4) = r;
    } else if (i4 < E) {
        for (int e = i4; e < E; e++) g_rank[e] = atomicAdd(&g_deg[edst[e]], 1);
    }
}

// ---------------- CSR scan ----------------------------------------------------
__global__ void scan1_kernel(int n) {
    __shared__ int wsum[32];
    int tid  = threadIdx.x;
    int lane = tid & 31;
    int w    = tid >> 5;
    int i = blockIdx.x * 1024 + tid;
    int v = (i < n) ? g_deg[i] : 0;
    int s = v;
#pragma unroll
    for (int o = 1; o < 32; o <<= 1) {
        int t = __shfl_up_sync(0xffffffffu, s, o);
        if (lane >= o) s += t;
    }
    if (lane == 31) wsum[w] = s;
    __syncthreads();
    if (w == 0) {
        int ws = wsum[lane];
#pragma unroll
        for (int o = 1; o < 32; o <<= 1) {
            int t = __shfl_up_sync(0xffffffffu, ws, o);
            if (lane >= o) ws += t;
        }
        wsum[lane] = ws;
    }
    __syncthreads();
    int base = (w > 0) ? wsum[w - 1] : 0;
    int incl = s + base;
    if (i < n) g_off[i] = incl - v;
    if (tid == 1023) g_bsum[blockIdx.x] = incl;
}

__global__ void scan3_kernel(int n, int N) {
    __shared__ int wsums[32];
    __shared__ int sbase;
    int bid = blockIdx.x, tid = threadIdx.x;
    int lane = tid & 31, w = tid >> 5;
    int v = (tid < bid) ? g_bsum[tid] : 0;
#pragma unroll
    for (int o = 16; o > 0; o >>= 1) v += __shfl_xor_sync(0xffffffffu, v, o);
    if (lane == 0) wsums[w] = v;
    __syncthreads();
    if (w == 0) {
        int s = wsums[lane];
#pragma unroll
        for (int o = 16; o > 0; o >>= 1) s += __shfl_xor_sync(0xffffffffu, s, o);
        if (lane == 0) sbase = s;
    }
    __syncthreads();
    int i = bid * 1024 + tid;
    if (i < n) {
        g_off[i] = g_off[i] + sbase;
        g_deg[i] = 0;                                // restore invariant
    }
}

__global__ void scatter_kernel(const int* __restrict__ esrc,
                               const int* __restrict__ edst,
                               const float* __restrict__ ew, int E) {
    int i = blockIdx.x * blockDim.x + threadIdx.x;
    int i4 = i * 4;
    if (i4 + 4 <= E) {
        int4   s = *(const int4*)(esrc + i4);
        int4   d = *(const int4*)(edst + i4);
        float4 w = *(const float4*)(ew + i4);
        int4   r = *(const int4*)(g_rank + i4);
        g_edge[g_off[d.x] + r.x] = make_uint2((uint32_t)s.x, __float_as_uint(w.x));
        g_edge[g_off[d.y] + r.y] = make_uint2((uint32_t)s.y, __float_as_uint(w.y));
        g_edge[g_off[d.z] + r.z] = make_uint2((uint32_t)s.z, __float_as_uint(w.z));
        g_edge[g_off[d.w] + r.w] = make_uint2((uint32_t)s.w, __float_as_uint(w.w));
    } else if (i4 < E) {
        for (int e = i4; e < E; e++) {
            g_edge[g_off[edst[e]] + g_rank[e]] =
                make_uint2((uint32_t)esrc[e], __float_as_uint(ew[e]));
        }
    }
}

// ---------------- SpMM: warp per dst row; hin = fp16((1+eps)x + agg) ---------
__global__ void spmm_kernel(int N, int Mpad) {
    int warp = (blockIdx.x * blockDim.x + threadIdx.x) >> 5;
    int lane = threadIdx.x & 31;
    if (warp >= Mpad) return;
    uint2* outp = (uint2*)(g_hin + (size_t)warp * (D_IN / 2));
    if (warp >= N) { outp[lane] = make_uint2(0, 0); return; }
    float ax = 0.f, ay = 0.f, az = 0.f, aw = 0.f;
    int e0 = g_off[warp], e1 = g_off[warp + 1];
    int e = e0;
#pragma unroll 1
    for (; e + 4 <= e1; e += 4) {
        uint2 p0 = g_edge[e],     p1 = g_edge[e + 1];
        uint2 p2 = g_edge[e + 2], p3 = g_edge[e + 3];
        float w0 = __uint_as_float(p0.y), w1 = __uint_as_float(p1.y);
        float w2 = __uint_as_float(p2.y), w3 = __uint_as_float(p3.y);
        uint2 u0 = ((const uint2*)(g_xh + (size_t)p0.x * 64))[lane];
        uint2 u1 = ((const uint2*)(g_xh + (size_t)p1.x * 64))[lane];
        uint2 u2 = ((const uint2*)(g_xh + (size_t)p2.x * 64))[lane];
        uint2 u3 = ((const uint2*)(g_xh + (size_t)p3.x * 64))[lane];
        float2 a0 = __half22float2(*(__half2*)&u0.x);
        float2 b0 = __half22float2(*(__half2*)&u0.y);
        float2 a1 = __half22float2(*(__half2*)&u1.x);
        float2 b1 = __half22float2(*(__half2*)&u1.y);
        float2 a2 = __half22float2(*(__half2*)&u2.x);
        float2 b2 = __half22float2(*(__half2*)&u2.y);
        float2 a3 = __half22float2(*(__half2*)&u3.x);
        float2 b3 = __half22float2(*(__half2*)&u3.y);
        ax = fmaf(w0, a0.x, ax); ay = fmaf(w0, a0.y, ay);
        az = fmaf(w0, b0.x, az); aw = fmaf(w0, b0.y, aw);
        ax = fmaf(w1, a1.x, ax); ay = fmaf(w1, a1.y, ay);
        az = fmaf(w1, b1.x, az); aw = fmaf(w1, b1.y, aw);
        ax = fmaf(w2, a2.x, ax); ay = fmaf(w2, a2.y, ay);
        az = fmaf(w2, b2.x, az); aw = fmaf(w2, b2.y, aw);
        ax = fmaf(w3, a3.x, ax); ay = fmaf(w3, a3.y, ay);
        az = fmaf(w3, b3.x, az); aw = fmaf(w3, b3.y, aw);
    }
#pragma unroll 1
    for (; e < e1; e++) {
        uint2 pe = g_edge[e];
        float w  = __uint_as_float(pe.y);
        uint2 u = ((const uint2*)(g_xh + (size_t)pe.x * 64))[lane];
        float2 v0 = __half22float2(*(__half2*)&u.x);
        float2 v1 = __half22float2(*(__half2*)&u.y);
        ax = fmaf(w, v0.x, ax);
        ay = fmaf(w, v0.y, ay);
        az = fmaf(w, v1.x, az);
        aw = fmaf(w, v1.y, aw);
    }
    uint2 us = ((const uint2*)(g_xh + (size_t)warp * 64))[lane];
    float2 s0 = __half22float2(*(__half2*)&us.x);
    float2 s1 = __half22float2(*(__half2*)&us.y);
    const float c = 1.0f + 1e-9f;
    outp[lane] = make_uint2(pack_h2(fmaf(c, s0.x, ax), fmaf(c, s0.y, ay)),
                            pack_h2(fmaf(c, s1.x, az), fmaf(c, s1.y, aw)));
}

// ------- FP16 GEMM: 128m x 256n CTA tile, 512 thr (16 warps), BK=64 ----------
// Warp grid 2m x 8n; each warp computes 64x32 (same fragment code as before).
// smem: A 2x16KB | B 2x32KB | aux 2KB
#define SA_OFF(b) ((b) * 16384)
#define SB_OFF(b) (32768 + (b) * 32768)
#define ST_OFF    98304
#define SMEM_TOT  100352

// FUSE_BN: A src = g_h1h fp16; half2 BN+ReLU in the loader (depth-1 staging)
// STATS:   per-column fp32 sum/sumsq of C (rows < M) into g_sum/g_sq
template <bool FUSE_BN, bool STATS, int KDIM>   // KDIM in halfs
__device__ __forceinline__ void gemm_body(
    const uint32_t* __restrict__ Ah, const uint32_t* __restrict__ Bt,
    void* __restrict__ Cv, const float* __restrict__ bias,
    int M, int Mstore, int ncols)
{
    extern __shared__ char smem[];
    const uint32_t sb = smem_u32(smem);
    constexpr int NC  = KDIM / 64;
    constexpr int KW  = KDIM / 2;          // uint32 per row

    const int tid  = threadIdx.x;
    const int lane = tid & 31;
    const int wid  = tid >> 5;             // 0..15
    const int brow = blockIdx.y * 128;
    const int bcol = blockIdx.x * 256;
    const int lr   = tid >> 3;      // 0..63 (row base for loads)
    const int lc   = tid & 7;       // 16B chunk col

    uint4 stg[2];                   // FUSE_BN A staging (2 rows x 16B)

    // ---- loaders (512 threads) ----
    auto asyncA = [&](int c) {
#pragma unroll
        for (int i = 0; i < 2; i++) {
            int r = lr + 64 * i;
            uint32_t dst = sb + SA_OFF(c & 1) + r * 128 + ((lc ^ (r & 7)) << 4);
            const char* src = (const char*)(Ah + (size_t)(brow + r) * KW + c * 32)
                              + lc * 16;
            CP16(dst, src);
        }
    };
    auto ldgA = [&](int c) {
#pragma unroll
        for (int i = 0; i < 2; i++) {
            int r = lr + 64 * i;
            stg[i] = *(const uint4*)(Ah + (size_t)(brow + r) * KW + c * 32 + lc * 4);
        }
    };
    auto stsA = [&](int c) {
        const uint4 scv = *(const uint4*)(g_sch + c * 64 + lc * 8);
        const uint4 shv = *(const uint4*)(g_shh + c * 64 + lc * 8);
        const __half2* sc = (const __half2*)&scv;
        const __half2* sh = (const __half2*)&shv;
        const __half2 z = __floats2half2_rn(0.f, 0.f);
#pragma unroll
        for (int i = 0; i < 2; i++) {
            int r = lr + 64 * i;
            __half2* a = (__half2*)&stg[i];
            uint4 u;
            __half2 t0 = __hmax2(__hfma2(a[0], sc[0], sh[0]), z);
            __half2 t1 = __hmax2(__hfma2(a[1], sc[1], sh[1]), z);
            __half2 t2 = __hmax2(__hfma2(a[2], sc[2], sh[2]), z);
            __half2 t3 = __hmax2(__hfma2(a[3], sc[3], sh[3]), z);
            u.x = *(uint32_t*)&t0; u.y = *(uint32_t*)&t1;
            u.z = *(uint32_t*)&t2; u.w = *(uint32_t*)&t3;
            *(uint4*)(smem + SA_OFF(c & 1) + r * 128 + ((lc ^ (r & 7)) << 4)) = u;
        }
    };
    auto asyncB = [&](int c) {
#pragma unroll
        for (int i = 0; i < 4; i++) {
            int r = lr + 64 * i;        // 0..255
            uint32_t dst = sb + SB_OFF(c & 1) + r * 128 + ((lc ^ (r & 7)) << 4);
            const char* src = (const char*)(Bt + (size_t)(bcol + r) * KW + c * 32)
                              + lc * 16;
            CP16(dst, src);
        }
    };

    // ---- fragment addressing (warp: 64m x 32n) ----
    const int wm = wid & 1, wn = wid >> 1;       // wm 0..1, wn 0..7
    const int g = lane >> 2, tig = lane & 3;
    const int mrow = wm * 64 + (lane & 15);
    const int hiA  = lane >> 4;
    const int nrow = wn * 32 + ((lane >> 4) << 3) + (lane & 7);
    const int hiB  = (lane >> 3) & 1;

    float acc[4][4][4];
#pragma unroll
    for (int mf = 0; mf < 4; mf++)
#pragma unroll
        for (int nf = 0; nf < 4; nf++)
#pragma unroll
            for (int q = 0; q < 4; q++) acc[mf][nf][q] = 0.f;

    // ---- prologue ----
    if (FUSE_BN) { ldgA(0); stsA(0); } else asyncA(0);
    asyncB(0);
    CP_COMMIT();

    // ---- mainloop ----
#pragma unroll 1
    for (int c = 0; c < NC; c++) {
        const bool more = (c + 1) < NC;
        if (more) {
            if (FUSE_BN) ldgA(c + 1); else asyncA(c + 1);
            asyncB(c + 1);
            CP_COMMIT();
            CP_WAIT1();
        } else {
            CP_WAIT0();
        }
        __syncthreads();

        const uint32_t Ab = sb + SA_OFF(c & 1);
        const uint32_t Bb = sb + SB_OFF(c & 1);
#pragma unroll
        for (int ks = 0; ks < 4; ks++) {
            const int c0 = ks * 2;
            uint32_t af[4][4];
#pragma unroll
            for (int mf = 0; mf < 4; mf++) {
                int r = mrow + mf * 16;
                uint32_t ad = Ab + r * 128 + (((c0 + hiA) ^ (r & 7)) << 4);
                ldsm4(af[mf][0], af[mf][1], af[mf][2], af[mf][3], ad);
            }
            uint32_t bf[4][2];
#pragma unroll
            for (int p = 0; p < 2; p++) {
                int r = nrow + p * 16;
                uint32_t bd = Bb + r * 128 + (((c0 + hiB) ^ (r & 7)) << 4);
                ldsm4(bf[2 * p][0], bf[2 * p][1], bf[2 * p + 1][0], bf[2 * p + 1][1], bd);
            }
#pragma unroll
            for (int mf = 0; mf < 4; mf++)
#pragma unroll
                for (int nf = 0; nf < 4; nf++)
                    mma_f16(acc[mf][nf], af[mf], bf[nf]);
        }
        __syncthreads();
        if (more && FUSE_BN) stsA(c + 1);
    }

    // ---- epilogue ----
    float* s_sum = (float*)(smem + ST_OFF);      // 256 floats
    float* s_sq  = s_sum + 256;

    float2 bb[4];
#pragma unroll
    for (int nf = 0; nf < 4; nf++)
        bb[nf] = *(const float2*)(bias + bcol + wn * 32 + nf * 8 + 2 * tig);

    if (STATS) {
        if (tid < 256) { s_sum[tid] = 0.f; s_sq[tid] = 0.f; }
        __syncthreads();
    }

    float ls[4][2], lq[4][2];
#pragma unroll
    for (int nf = 0; nf < 4; nf++) {
        ls[nf][0] = 0.f; ls[nf][1] = 0.f;
        lq[nf][0] = 0.f; lq[nf][1] = 0.f;
    }

#pragma unroll
    for (int mf = 0; mf < 4; mf++) {
        int r0 = brow + wm * 64 + mf * 16 + g;
        int r1 = r0 + 8;
#pragma unroll
        for (int nf = 0; nf < 4; nf++) {
            int col = bcol + wn * 32 + nf * 8 + 2 * tig;
            float v0 = acc[mf][nf][0] + bb[nf].x;
            float v1 = acc[mf][nf][1] + bb[nf].y;
            float v2 = acc[mf][nf][2] + bb[nf].x;
            float v3 = acc[mf][nf][3] + bb[nf].y;
            if (STATS) {
                if (r0 < Mstore)
                    ((uint32_t*)Cv)[(size_t)r0 * (ncols / 2) + col / 2] = pack_h2(v0, v1);
                if (r1 < Mstore)
                    ((uint32_t*)Cv)[(size_t)r1 * (ncols / 2) + col / 2] = pack_h2(v2, v3);
                if (r0 < M) {
                    ls[nf][0] += v0; lq[nf][0] = fmaf(v0, v0, lq[nf][0]);
                    ls[nf][1] += v1; lq[nf][1] = fmaf(v1, v1, lq[nf][1]);
                }
                if (r1 < M) {
                    ls[nf][0] += v2; lq[nf][0] = fmaf(v2, v2, lq[nf][0]);
                    ls[nf][1] += v3; lq[nf][1] = fmaf(v3, v3, lq[nf][1]);
                }
            } else {
                float* C = (float*)Cv;
                if (r0 < Mstore)
                    *(float2*)(C + (size_t)r0 * ncols + col) = make_float2(v0, v1);
                if (r1 < Mstore)
                    *(float2*)(C + (size_t)r1 * ncols + col) = make_float2(v2, v3);
            }
        }
    }

    if (STATS) {
        // butterfly over g-lanes, then only g==0 lanes hit smem atomics
#pragma unroll
        for (int nf = 0; nf < 4; nf++)
#pragma unroll
            for (int j = 0; j < 2; j++) {
#pragma unroll
                for (int o = 4; o <= 16; o <<= 1) {
                    ls[nf][j] += __shfl_xor_sync(0xffffffffu, ls[nf][j], o);
                    lq[nf][j] += __shfl_xor_sync(0xffffffffu, lq[nf][j], o);
                }
            }
        if (g == 0) {
#pragma unroll
            for (int nf = 0; nf < 4; nf++) {
                int scol = wn * 32 + nf * 8 + 2 * tig;
                atomicAdd(&s_sum[scol],     ls[nf][0]);
                atomicAdd(&s_sum[scol + 1], ls[nf][1]);
                atomicAdd(&s_sq[scol],      lq[nf][0]);
                atomicAdd(&s_sq[scol + 1],  lq[nf][1]);
            }
        }
        __syncthreads();
        if (tid < 256) {
            atomicAdd(&g_sum[bcol + tid], s_sum[tid]);
            atomicAdd(&g_sq[bcol + tid],  s_sq[tid]);
        }
    }
}

// Wrappers: device-code references to scratch globals (NEVER pass __device__
// symbols as kernel arguments from host — HMM resolves them to host shadows).
__global__ __launch_bounds__(512, 1)
void gemm1_kernel(const float* __restrict__ bias, int M) {
    gemm_body<false, true, D_IN>(g_hin, g_w1t, g_h1h, bias, M, MPAD, D_HID);
}
__global__ __launch_bounds__(512, 1)
void gemm2_kernel(const float* __restrict__ bias, float* __restrict__ C, int M) {
    gemm_body<true, false, D_HID>(g_h1h, g_w2t, C, bias, M, M, D_OUT);
}

// -------- BN finalize: scale/shift from sums; re-zero sums for next replay ---
__global__ void finalize_kernel(const float* __restrict__ gamma,
                                const float* __restrict__ beta, int M) {
    int c = blockIdx.x * blockDim.x + threadIdx.x;
    if (c < D_HID) {
        float inv = 1.0f / (float)M;
        float m   = g_sum[c] * inv;
        float var = fmaxf(g_sq[c] * inv - m * m, 0.f);
        float r   = rsqrtf(var + 1e-5f);
        float sc  = r * gamma[c];
        g_sch[c] = __float2half(sc);
        g_shh[c] = __float2half(fmaf(-m, sc, beta[c]));
        g_sum[c] = 0.f;
        g_sq[c]  = 0.f;
    }
}

// ---------------- launch -----------------------------------------------------
extern "C" void kernel_launch(void* const* d_in, const int* in_sizes, int n_in,
                              void* d_out, int out_size) {
    const float* x     = (const float*)d_in[0];
    const int*   esrc  = (const int*)  d_in[1];
    const int*   edst  = (const int*)  d_in[2];
    const float* ew    = (const float*)d_in[3];
    const float* w1    = (const float*)d_in[4];
    const float* b1    = (const float*)d_in[5];
    const float* gamma = (const float*)d_in[6];
    const float* beta  = (const float*)d_in[7];
    const float* w2    = (const float*)d_in[8];
    const float* b2    = (const float*)d_in[9];
    float* out = (float*)d_out;

    int N = in_sizes[0] / D_IN;
    int E = in_sizes[1];
    if (N > NMAX) N = NMAX;
    if (E > EMAX) E = EMAX;

    int n1 = N + 1;
    int nb = (n1 + 1023) / 1024;
    int nx = N * (D_IN / 2);
    int e4 = (E + 3) / 4;

    cudaFuncSetAttribute(gemm1_kernel,
                         cudaFuncAttributeMaxDynamicSharedMemorySize, SMEM_TOT);
    cudaFuncSetAttribute(gemm2_kernel,
                         cudaFuncAttributeMaxDynamicSharedMemorySize, SMEM_TOT);

    // 1. merged prep (x->fp16 + w transposes + histogram + edge ranks)
    {
        int nblk = (nx + 255) / 256;
        int hblk = (e4 + 255) / 256;
        if (hblk > nblk) nblk = hblk;
        prep_kernel<<<nblk, 256>>>(x, w1, w2, edst, nx, E);
    }
    // 2-4. CSR build
    scan1_kernel<<<nb, 1024>>>(n1);
    scan3_kernel<<<nb, 1024>>>(n1, N);
    scatter_kernel<<<((e4 + 255) / 256), 256>>>(esrc, edst, ew, E);

    // 5. SpMM + (1+eps)x -> fp16 packed
    {
        int blocks = (MPAD * 32 + 255) / 256;
        spmm_kernel<<<blocks, 256>>>(N, MPAD);
    }
    // 6. GEMM1: hin @ w1 -> h1h fp16 (+bias, +BN stats); 128x256 tiles
    {
        dim3 grid(D_HID / 256, MPAD / 128);
        gemm1_kernel<<<grid, 512, SMEM_TOT>>>(b1, N);
    }
    // 7. BN scale/shift (fp16) + sums re-zero
    finalize_kernel<<<1, 512>>>(gamma, beta, N);
    // 8. GEMM2: relu(BN(h1h)) @ w2 -> out fp32 (+bias); 128x256 tiles
    {
        dim3 grid(D_OUT / 256, MPAD / 128);
        gemm2_kernel<<<grid, 512, SMEM_TOT>>>(b2, out, N);
    }
}

// round 17
// speedup vs baseline: 1.0974x; 1.0974x over previous
#include <cuda_runtime.h>
#include <cuda_fp16.h>
#include <cstdint>

#define D_IN  128
#define D_HID 512
#define D_OUT 256
#define NMAX  100000
#define EMAX  1600000
#define MPAD  100096   // ceil(100000/128)*128

// ---------------- scratch (device globals; zero-initialized at load) --------
// Invariants across graph replays: g_deg==0 on entry (re-zeroed by scan3);
// g_sum/g_sq==0 on entry (re-zeroed by prep).
__device__ int      g_deg[NMAX + 1];
__device__ int      g_off[NMAX + 1];
__device__ int      g_rank[EMAX];
__device__ int      g_bsum[128];
__device__ uint2    g_edge[EMAX];                          // (src, w-bits)
__device__ uint32_t g_xh [(size_t)NMAX * (D_IN / 2)];      // x fp16 [n][k/2]
__device__ uint32_t g_hin[(size_t)MPAD * (D_IN / 2)];      // half2 [m][k/2]
__device__ uint32_t g_h1h[(size_t)MPAD * (D_HID / 2)];     // h1 fp16 pre-BN
__device__ uint32_t g_w1t[(size_t)D_HID * (D_IN / 2)];     // w1^T fp16 [n][k/2]
__device__ uint32_t g_w2t[(size_t)D_OUT * (D_HID / 2)];    // w2^T fp16 [n][k/2]
__device__ float    g_sum[D_HID], g_sq[D_HID];

__device__ __forceinline__ uint32_t pack_h2(float a, float b) {
    __half2 h = __floats2half2_rn(a, b);
    return *reinterpret_cast<uint32_t*>(&h);
}
__device__ __forceinline__ uint32_t smem_u32(const void* p) {
    uint32_t a;
    asm("{ .reg .u64 t; cvta.to.shared.u64 t, %1; cvt.u32.u64 %0, t; }"
        : "=r"(a) : "l"(p));
    return a;
}
#define CP16(dst, src) \
    asm volatile("cp.async.cg.shared.global [%0], [%1], 16;" :: "r"(dst), "l"(src))
#define CP_COMMIT() asm volatile("cp.async.commit_group;" ::: "memory")
#define CP_WAIT0()  asm volatile("cp.async.wait_group 0;" ::: "memory")
#define CP_WAIT1()  asm volatile("cp.async.wait_group 1;" ::: "memory")

__device__ __forceinline__ void ldsm4(uint32_t& r0, uint32_t& r1,
                                      uint32_t& r2, uint32_t& r3, uint32_t a) {
    asm volatile("ldmatrix.sync.aligned.m8n8.x4.shared.b16 {%0,%1,%2,%3}, [%4];"
                 : "=r"(r0), "=r"(r1), "=r"(r2), "=r"(r3) : "r"(a));
}
__device__ __forceinline__ void mma_f16(float d[4], const uint32_t a[4],
                                        const uint32_t b[2]) {
    asm volatile(
        "mma.sync.aligned.m16n8k16.row.col.f32.f16.f16.f32 "
        "{%0,%1,%2,%3},{%4,%5,%6,%7},{%8,%9},{%0,%1,%2,%3};\n"
        : "+f"(d[0]), "+f"(d[1]), "+f"(d[2]), "+f"(d[3])
        : "r"(a[0]), "r"(a[1]), "r"(a[2]), "r"(a[3]),
          "r"(b[0]), "r"(b[1]));
}

// ------- merged prep: x->fp16 + w^T packs + histogram/ranks + zero sums ------
__global__ void prep_kernel(const float* __restrict__ x,
                            const float* __restrict__ w1,
                            const float* __restrict__ w2,
                            const int* __restrict__ edst,
                            int nx, int E) {
    int i = blockIdx.x * 256 + threadIdx.x;
    if (i < nx) {
        float2 v = ((const float2*)x)[i];
        g_xh[i] = pack_h2(v.x, v.y);
    }
    if (i < D_HID) { g_sum[i] = 0.f; g_sq[i] = 0.f; }
    if (i < D_HID * (D_IN / 2)) {
        int n = i / (D_IN / 2), kc = i % (D_IN / 2);
        g_w1t[i] = pack_h2(w1[(size_t)(2 * kc) * D_HID + n],
                           w1[(size_t)(2 * kc + 1) * D_HID + n]);
    }
    if (i < D_OUT * (D_HID / 2)) {
        int n = i / (D_HID / 2), kc = i % (D_HID / 2);
        g_w2t[i] = pack_h2(w2[(size_t)(2 * kc) * D_OUT + n],
                           w2[(size_t)(2 * kc + 1) * D_OUT + n]);
    }
    int i4 = i * 4;
    if (i4 + 4 <= E) {
        int4 d = *(const int4*)(edst + i4);
        int4 r;
        r.x = atomicAdd(&g_deg[d.x], 1);
        r.y = atomicAdd(&g_deg[d.y], 1);
        r.z = atomicAdd(&g_deg[d.z], 1);
        r.w = atomicAdd(&g_deg[d.w], 1);
        *(int4*)(g_rank + i4) = r;
    } else if (i4 < E) {
        for (int e = i4; e < E; e++) g_rank[e] = atomicAdd(&g_deg[edst[e]], 1);
    }
}

// ---------------- CSR scan ----------------------------------------------------
__global__ void scan1_kernel(int n) {
    __shared__ int wsum[32];
    int tid  = threadIdx.x;
    int lane = tid & 31;
    int w    = tid >> 5;
    int i = blockIdx.x * 1024 + tid;
    int v = (i < n) ? g_deg[i] : 0;
    int s = v;
#pragma unroll
    for (int o = 1; o < 32; o <<= 1) {
        int t = __shfl_up_sync(0xffffffffu, s, o);
        if (lane >= o) s += t;
    }
    if (lane == 31) wsum[w] = s;
    __syncthreads();
    if (w == 0) {
        int ws = wsum[lane];
#pragma unroll
        for (int o = 1; o < 32; o <<= 1) {
            int t = __shfl_up_sync(0xffffffffu, ws, o);
            if (lane >= o) ws += t;
        }
        wsum[lane] = ws;
    }
    __syncthreads();
    int base = (w > 0) ? wsum[w - 1] : 0;
    int incl = s + base;
    if (i < n) g_off[i] = incl - v;
    if (tid == 1023) g_bsum[blockIdx.x] = incl;
}

__global__ void scan3_kernel(int n, int N) {
    __shared__ int wsums[32];
    __shared__ int sbase;
    int bid = blockIdx.x, tid = threadIdx.x;
    int lane = tid & 31, w = tid >> 5;
    int v = (tid < bid) ? g_bsum[tid] : 0;
#pragma unroll
    for (int o = 16; o > 0; o >>= 1) v += __shfl_xor_sync(0xffffffffu, v, o);
    if (lane == 0) wsums[w] = v;
    __syncthreads();
    if (w == 0) {
        int s = wsums[lane];
#pragma unroll
        for (int o = 16; o > 0; o >>= 1) s += __shfl_xor_sync(0xffffffffu, s, o);
        if (lane == 0) sbase = s;
    }
    __syncthreads();
    int i = bid * 1024 + tid;
    if (i < n) {
        g_off[i] = g_off[i] + sbase;
        g_deg[i] = 0;                                // restore invariant
    }
}

__global__ void scatter_kernel(const int* __restrict__ esrc,
                               const int* __restrict__ edst,
                               const float* __restrict__ ew, int E) {
    int i = blockIdx.x * blockDim.x + threadIdx.x;
    int i4 = i * 4;
    if (i4 + 4 <= E) {
        int4   s = *(const int4*)(esrc + i4);
        int4   d = *(const int4*)(edst + i4);
        float4 w = *(const float4*)(ew + i4);
        int4   r = *(const int4*)(g_rank + i4);
        g_edge[g_off[d.x] + r.x] = make_uint2((uint32_t)s.x, __float_as_uint(w.x));
        g_edge[g_off[d.y] + r.y] = make_uint2((uint32_t)s.y, __float_as_uint(w.y));
        g_edge[g_off[d.z] + r.z] = make_uint2((uint32_t)s.z, __float_as_uint(w.z));
        g_edge[g_off[d.w] + r.w] = make_uint2((uint32_t)s.w, __float_as_uint(w.w));
    } else if (i4 < E) {
        for (int e = i4; e < E; e++) {
            g_edge[g_off[edst[e]] + g_rank[e]] =
                make_uint2((uint32_t)esrc[e], __float_as_uint(ew[e]));
        }
    }
}

// ---------------- SpMM: warp per dst row; hin = fp16((1+eps)x + agg) ---------
__global__ void spmm_kernel(int N, int Mpad) {
    int warp = (blockIdx.x * blockDim.x + threadIdx.x) >> 5;
    int lane = threadIdx.x & 31;
    if (warp >= Mpad) return;
    uint2* outp = (uint2*)(g_hin + (size_t)warp * (D_IN / 2));
    if (warp >= N) { outp[lane] = make_uint2(0, 0); return; }
    float ax = 0.f, ay = 0.f, az = 0.f, aw = 0.f;
    int e0 = g_off[warp], e1 = g_off[warp + 1];
    int e = e0;
#pragma unroll 1
    for (; e + 4 <= e1; e += 4) {
        uint2 p0 = g_edge[e],     p1 = g_edge[e + 1];
        uint2 p2 = g_edge[e + 2], p3 = g_edge[e + 3];
        float w0 = __uint_as_float(p0.y), w1 = __uint_as_float(p1.y);
        float w2 = __uint_as_float(p2.y), w3 = __uint_as_float(p3.y);
        uint2 u0 = ((const uint2*)(g_xh + (size_t)p0.x * 64))[lane];
        uint2 u1 = ((const uint2*)(g_xh + (size_t)p1.x * 64))[lane];
        uint2 u2 = ((const uint2*)(g_xh + (size_t)p2.x * 64))[lane];
        uint2 u3 = ((const uint2*)(g_xh + (size_t)p3.x * 64))[lane];
        float2 a0 = __half22float2(*(__half2*)&u0.x);
        float2 b0 = __half22float2(*(__half2*)&u0.y);
        float2 a1 = __half22float2(*(__half2*)&u1.x);
        float2 b1 = __half22float2(*(__half2*)&u1.y);
        float2 a2 = __half22float2(*(__half2*)&u2.x);
        float2 b2 = __half22float2(*(__half2*)&u2.y);
        float2 a3 = __half22float2(*(__half2*)&u3.x);
        float2 b3 = __half22float2(*(__half2*)&u3.y);
        ax = fmaf(w0, a0.x, ax); ay = fmaf(w0, a0.y, ay);
        az = fmaf(w0, b0.x, az); aw = fmaf(w0, b0.y, aw);
        ax = fmaf(w1, a1.x, ax); ay = fmaf(w1, a1.y, ay);
        az = fmaf(w1, b1.x, az); aw = fmaf(w1, b1.y, aw);
        ax = fmaf(w2, a2.x, ax); ay = fmaf(w2, a2.y, ay);
        az = fmaf(w2, b2.x, az); aw = fmaf(w2, b2.y, aw);
        ax = fmaf(w3, a3.x, ax); ay = fmaf(w3, a3.y, ay);
        az = fmaf(w3, b3.x, az); aw = fmaf(w3, b3.y, aw);
    }
#pragma unroll 1
    for (; e < e1; e++) {
        uint2 pe = g_edge[e];
        float w  = __uint_as_float(pe.y);
        uint2 u = ((const uint2*)(g_xh + (size_t)pe.x * 64))[lane];
        float2 v0 = __half22float2(*(__half2*)&u.x);
        float2 v1 = __half22float2(*(__half2*)&u.y);
        ax = fmaf(w, v0.x, ax);
        ay = fmaf(w, v0.y, ay);
        az = fmaf(w, v1.x, az);
        aw = fmaf(w, v1.y, aw);
    }
    uint2 us = ((const uint2*)(g_xh + (size_t)warp * 64))[lane];
    float2 s0 = __half22float2(*(__half2*)&us.x);
    float2 s1 = __half22float2(*(__half2*)&us.y);
    const float c = 1.0f + 1e-9f;
    outp[lane] = make_uint2(pack_h2(fmaf(c, s0.x, ax), fmaf(c, s0.y, ay)),
                            pack_h2(fmaf(c, s1.x, az), fmaf(c, s1.y, aw)));
}

// ---------------- FP16 GEMM: 128x128 CTA, BK=64, cp.async + ldmatrix ---------
// smem: A 2x16KB | B 2x16KB | aux 2KB (stats OR BN scale/shift)
#define SA_OFF(b) ((b) * 16384)
#define SB_OFF(b) (32768 + (b) * 16384)
#define AUX_OFF   65536
#define SMEM_TOT  67584

// FUSE_BN: A src = g_h1h fp16; CTA computes BN scale/shift (fp16) into smem
//          from g_sum/g_sq/gamma/beta, then applies in the A loader (depth-1).
// STATS:   per-column fp32 sum/sumsq of C (rows < M) into g_sum/g_sq
template <bool FUSE_BN, bool STATS, int KDIM>   // KDIM in halfs
__device__ __forceinline__ void gemm_body(
    const uint32_t* __restrict__ Ah, const uint32_t* __restrict__ Bt,
    void* __restrict__ Cv, const float* __restrict__ bias,
    const float* __restrict__ gamma, const float* __restrict__ beta,
    int M, int Mstore, int ncols)
{
    extern __shared__ char smem[];
    const uint32_t sb = smem_u32(smem);
    constexpr int NC  = KDIM / 64;
    constexpr int KW  = KDIM / 2;          // uint32 per row

    const int tid  = threadIdx.x;
    const int lane = tid & 31;
    const int wid  = tid >> 5;
    const int brow = blockIdx.y * 128;
    const int bcol = blockIdx.x * 128;
    const int lr   = tid >> 3;      // 0..31 (row base for loads)
    const int lc   = tid & 7;       // 16B chunk col

    __half* s_sch = (__half*)(smem + AUX_OFF);          // 512 halves
    __half* s_shh = (__half*)(smem + AUX_OFF + 1024);   // 512 halves

    // ---- FUSE_BN prologue: compute BN scale/shift into smem -----------------
    if (FUSE_BN) {
#pragma unroll
        for (int c = tid; c < D_HID; c += 256) {
            float inv = 1.0f / (float)M;
            float m   = g_sum[c] * inv;
            float var = fmaxf(g_sq[c] * inv - m * m, 0.f);
            float r   = rsqrtf(var + 1e-5f);
            float sc  = r * gamma[c];
            s_sch[c] = __float2half(sc);
            s_shh[c] = __float2half(fmaf(-m, sc, beta[c]));
        }
        __syncthreads();
    }

    uint4 stg[4];                   // FUSE_BN A staging (4 rows x 16B)

    // ---- loaders ----
    auto asyncA = [&](int c) {
#pragma unroll
        for (int i = 0; i < 4; i++) {
            int r = lr + 32 * i;
            uint32_t dst = sb + SA_OFF(c & 1) + r * 128 + ((lc ^ (r & 7)) << 4);
            const char* src = (const char*)(Ah + (size_t)(brow + r) * KW + c * 32)
                              + lc * 16;
            CP16(dst, src);
        }
    };
    auto ldgA = [&](int c) {
#pragma unroll
        for (int i = 0; i < 4; i++) {
            int r = lr + 32 * i;
            stg[i] = *(const uint4*)(Ah + (size_t)(brow + r) * KW + c * 32 + lc * 4);
        }
    };
    auto stsA = [&](int c) {
        const uint4 scv = *(const uint4*)(s_sch + c * 64 + lc * 8);
        const uint4 shv = *(const uint4*)(s_shh + c * 64 + lc * 8);
        const __half2* sc = (const __half2*)&scv;
        const __half2* sh = (const __half2*)&shv;
        const __half2 z = __floats2half2_rn(0.f, 0.f);
#pragma unroll
        for (int i = 0; i < 4; i++) {
            int r = lr + 32 * i;
            __half2* a = (__half2*)&stg[i];
            uint4 u;
            __half2 t0 = __hmax2(__hfma2(a[0], sc[0], sh[0]), z);
            __half2 t1 = __hmax2(__hfma2(a[1], sc[1], sh[1]), z);
            __half2 t2 = __hmax2(__hfma2(a[2], sc[2], sh[2]), z);
            __half2 t3 = __hmax2(__hfma2(a[3], sc[3], sh[3]), z);
            u.x = *(uint32_t*)&t0; u.y = *(uint32_t*)&t1;
            u.z = *(uint32_t*)&t2; u.w = *(uint32_t*)&t3;
            *(uint4*)(smem + SA_OFF(c & 1) + r * 128 + ((lc ^ (r & 7)) << 4)) = u;
        }
    };
    auto asyncB = [&](int c) {
#pragma unroll
        for (int i = 0; i < 4; i++) {
            int r = lr + 32 * i;
            uint32_t dst = sb + SB_OFF(c & 1) + r * 128 + ((lc ^ (r & 7)) << 4);
            const char* src = (const char*)(Bt + (size_t)(bcol + r) * KW + c * 32)
                              + lc * 16;
            CP16(dst, src);
        }
    };

    // ---- fragment addressing ----
    const int wm = wid & 1, wn = wid >> 1;
    const int g = lane >> 2, tig = lane & 3;
    const int mrow = wm * 64 + (lane & 15);
    const int hiA  = lane >> 4;
    const int nrow = wn * 32 + ((lane >> 4) << 3) + (lane & 7);
    const int hiB  = (lane >> 3) & 1;

    float acc[4][4][4];
#pragma unroll
    for (int mf = 0; mf < 4; mf++)
#pragma unroll
        for (int nf = 0; nf < 4; nf++)
#pragma unroll
            for (int q = 0; q < 4; q++) acc[mf][nf][q] = 0.f;

    // ---- prologue ----
    if (FUSE_BN) { ldgA(0); stsA(0); } else asyncA(0);
    asyncB(0);
    CP_COMMIT();

    // ---- mainloop ----
#pragma unroll 1
    for (int c = 0; c < NC; c++) {
        const bool more = (c + 1) < NC;
        if (more) {
            if (FUSE_BN) ldgA(c + 1); else asyncA(c + 1);
            asyncB(c + 1);
            CP_COMMIT();
            CP_WAIT1();
        } else {
            CP_WAIT0();
        }
        __syncthreads();

        const uint32_t Ab = sb + SA_OFF(c & 1);
        const uint32_t Bb = sb + SB_OFF(c & 1);
#pragma unroll
        for (int ks = 0; ks < 4; ks++) {
            const int c0 = ks * 2;
            uint32_t af[4][4];
#pragma unroll
            for (int mf = 0; mf < 4; mf++) {
                int r = mrow + mf * 16;
                uint32_t ad = Ab + r * 128 + (((c0 + hiA) ^ (r & 7)) << 4);
                ldsm4(af[mf][0], af[mf][1], af[mf][2], af[mf][3], ad);
            }
            uint32_t bf[4][2];
#pragma unroll
            for (int p = 0; p < 2; p++) {
                int r = nrow + p * 16;
                uint32_t bd = Bb + r * 128 + (((c0 + hiB) ^ (r & 7)) << 4);
                ldsm4(bf[2 * p][0], bf[2 * p][1], bf[2 * p + 1][0], bf[2 * p + 1][1], bd);
            }
#pragma unroll
            for (int mf = 0; mf < 4; mf++)
#pragma unroll
                for (int nf = 0; nf < 4; nf++)
                    mma_f16(acc[mf][nf], af[mf], bf[nf]);
        }
        __syncthreads();
        if (more && FUSE_BN) stsA(c + 1);
    }

    // ---- epilogue ----
    float* s_sum = (float*)(smem + AUX_OFF);
    float* s_sq  = s_sum + 128;

    float2 bb[4];
#pragma unroll
    for (int nf = 0; nf < 4; nf++)
        bb[nf] = *(const float2*)(bias + bcol + wn * 32 + nf * 8 + 2 * tig);

    if (STATS) {
        if (tid < 128) { s_sum[tid] = 0.f; s_sq[tid] = 0.f; }
        __syncthreads();
    }

    float ls[4][2], lq[4][2];
#pragma unroll
    for (int nf = 0; nf < 4; nf++) {
        ls[nf][0] = 0.f; ls[nf][1] = 0.f;
        lq[nf][0] = 0.f; lq[nf][1] = 0.f;
    }

#pragma unroll
    for (int mf = 0; mf < 4; mf++) {
        int r0 = brow + wm * 64 + mf * 16 + g;
        int r1 = r0 + 8;
#pragma unroll
        for (int nf = 0; nf < 4; nf++) {
            int col = bcol + wn * 32 + nf * 8 + 2 * tig;
            float v0 = acc[mf][nf][0] + bb[nf].x;
            float v1 = acc[mf][nf][1] + bb[nf].y;
            float v2 = acc[mf][nf][2] + bb[nf].x;
            float v3 = acc[mf][nf][3] + bb[nf].y;
            if (STATS) {
                if (r0 < Mstore)
                    ((uint32_t*)Cv)[(size_t)r0 * (ncols / 2) + col / 2] = pack_h2(v0, v1);
                if (r1 < Mstore)
                    ((uint32_t*)Cv)[(size_t)r1 * (ncols / 2) + col / 2] = pack_h2(v2, v3);
                if (r0 < M) {
                    ls[nf][0] += v0; lq[nf][0] = fmaf(v0, v0, lq[nf][0]);
                    ls[nf][1] += v1; lq[nf][1] = fmaf(v1, v1, lq[nf][1]);
                }
                if (r1 < M) {
                    ls[nf][0] += v2; lq[nf][0] = fmaf(v2, v2, lq[nf][0]);
                    ls[nf][1] += v3; lq[nf][1] = fmaf(v3, v3, lq[nf][1]);
                }
            } else {
                float* C = (float*)Cv;
                if (r0 < Mstore)
                    *(float2*)(C + (size_t)r0 * ncols + col) = make_float2(v0, v1);
                if (r1 < Mstore)
                    *(float2*)(C + (size_t)r1 * ncols + col) = make_float2(v2, v3);
            }
        }
    }

    if (STATS) {
#pragma unroll
        for (int nf = 0; nf < 4; nf++)
#pragma unroll
            for (int j = 0; j < 2; j++) {
#pragma unroll
                for (int o = 4; o <= 16; o <<= 1) {
                    ls[nf][j] += __shfl_xor_sync(0xffffffffu, ls[nf][j], o);
                    lq[nf][j] += __shfl_xor_sync(0xffffffffu, lq[nf][j], o);
                }
            }
        if (g == 0) {
#pragma unroll
            for (int nf = 0; nf < 4; nf++) {
                int scol = wn * 32 + nf * 8 + 2 * tig;
                atomicAdd(&s_sum[scol],     ls[nf][0]);
                atomicAdd(&s_sum[scol + 1], ls[nf][1]);
                atomicAdd(&s_sq[scol],      lq[nf][0]);
                atomicAdd(&s_sq[scol + 1],  lq[nf][1]);
            }
        }
        __syncthreads();
        if (tid < 128) {
            atomicAdd(&g_sum[bcol + tid], s_sum[tid]);
            atomicAdd(&g_sq[bcol + tid],  s_sq[tid]);
        }
    }
}

// Wrappers: device-code references to scratch globals (NEVER pass __device__
// symbols as kernel arguments from host — HMM resolves them to host shadows).
__global__ __launch_bounds__(256, 2)
void gemm1_kernel(const float* __restrict__ bias, int M) {
    gemm_body<false, true, D_IN>(g_hin, g_w1t, g_h1h, bias,
                                 nullptr, nullptr, M, MPAD, D_HID);
}
__global__ __launch_bounds__(256, 2)
void gemm2_kernel(const float* __restrict__ bias,
                  const float* __restrict__ gamma,
                  const float* __restrict__ beta,
                  float* __restrict__ C, int M) {
    gemm_body<true, false, D_HID>(g_h1h, g_w2t, C, bias,
                                  gamma, beta, M, M, D_OUT);
}

// ---------------- launch -----------------------------------------------------
extern "C" void kernel_launch(void* const* d_in, const int* in_sizes, int n_in,
                              void* d_out, int out_size) {
    const float* x     = (const float*)d_in[0];
    const int*   esrc  = (const int*)  d_in[1];
    const int*   edst  = (const int*)  d_in[2];
    const float* ew    = (const float*)d_in[3];
    const float* w1    = (const float*)d_in[4];
    const float* b1    = (const float*)d_in[5];
    const float* gamma = (const float*)d_in[6];
    const float* beta  = (const float*)d_in[7];
    const float* w2    = (const float*)d_in[8];
    const float* b2    = (const float*)d_in[9];
    float* out = (float*)d_out;

    int N = in_sizes[0] / D_IN;
    int E = in_sizes[1];
    if (N > NMAX) N = NMAX;
    if (E > EMAX) E = EMAX;

    int n1 = N + 1;
    int nb = (n1 + 1023) / 1024;
    int nx = N * (D_IN / 2);
    int e4 = (E + 3) / 4;

    cudaFuncSetAttribute(gemm1_kernel,
                         cudaFuncAttributeMaxDynamicSharedMemorySize, SMEM_TOT);
    cudaFuncSetAttribute(gemm2_kernel,
                         cudaFuncAttributeMaxDynamicSharedMemorySize, SMEM_TOT);

    // 1. merged prep (x->fp16 + w transposes + histogram/ranks + zero sums)
    {
        int nblk = (nx + 255) / 256;
        int hblk = (e4 + 255) / 256;
        if (hblk > nblk) nblk = hblk;
        prep_kernel<<<nblk, 256>>>(x, w1, w2, edst, nx, E);
    }
    // 2-4. CSR build
    scan1_kernel<<<nb, 1024>>>(n1);
    scan3_kernel<<<nb, 1024>>>(n1, N);
    scatter_kernel<<<((e4 + 255) / 256), 256>>>(esrc, edst, ew, E);

    // 5. SpMM + (1+eps)x -> fp16 packed
    {
        int blocks = (MPAD * 32 + 255) / 256;
        spmm_kernel<<<blocks, 256>>>(N, MPAD);
    }
    // 6. GEMM1: hin @ w1 -> h1h fp16 (+bias, +BN stats fp32)
    {
        dim3 grid(D_HID / 128, MPAD / 128);
        gemm1_kernel<<<grid, 256, SMEM_TOT>>>(b1, N);
    }
    // 7. GEMM2: computes BN scale/shift in-CTA, relu(BN(h1h)) @ w2 -> out
    {
        dim3 grid(D_OUT / 128, MPAD / 128);
        gemm2_kernel<<<grid, 256, SMEM_TOT>>>(b2, gamma, beta, out, N);
    }
}